// round 5
// baseline (speedup 1.0000x reference)
#include <cuda_runtime.h>
#include <cuda_bf16.h>
#include <math.h>

#define NN   1024
#define RANK 64
#define MM   1024
#define FCH  32    // f-chunk per thread
#define NB   128   // n per block

// Scratch: FFT of softplus(H), layout [r][f].
__device__ float2 d_Hf[RANK * MM];
// Input dtype flag: 1 = float32, 0 = bfloat16.
__device__ int d_isf32;

// ---------------------------------------------------------------------------
// Detect input dtype from first 128 elements of W read AS bf16 (256 bytes —
// safe under both interpretations). bf16 U[0,1) stays in [0,1); f32 bits
// reinterpreted as bf16 halves produce negatives/huge exponents.
// ---------------------------------------------------------------------------
__global__ void detect_kernel(const void* __restrict__ W, int nW) {
    if (threadIdx.x != 0 || blockIdx.x != 0) return;
    const __nv_bfloat16* p = (const __nv_bfloat16*)W;
    int cnt = nW < 128 ? nW : 128;
    int f32 = 0;
    for (int i = 0; i < cnt; i++) {
        float v = __bfloat162float(p[i]);
        if (!(v >= 0.0f && v < 2.0f)) f32 = 1;
    }
    d_isf32 = f32;
}

__device__ __forceinline__ float load_in(const void* p, int i, int isf32) {
    if (isf32) return ((const float*)p)[i];
    return __bfloat162float(((const __nv_bfloat16*)p)[i]);
}

// ---------------------------------------------------------------------------
// 1024-point radix-2 DIT FFT of softplus(H[r,:]) per block (numpy sign
// convention: X[f] = sum_k x[k] e^{-2*pi*i*f*k/M}).
// ---------------------------------------------------------------------------
__global__ void fft_kernel(const void* __restrict__ H, int nH) {
    __shared__ float re[MM];
    __shared__ float im[MM];
    int r = blockIdx.x;
    int isf32 = d_isf32;

    for (int i = threadIdx.x; i < MM; i += blockDim.x) {
        int src = r * MM + i;
        float x = (src < nH) ? load_in(H, src, isf32) : 0.0f;
        float v = log1pf(expf(x));                 // softplus
        int j = (int)(__brev((unsigned)i) >> 22);  // 10-bit reversal
        re[j] = v;
        im[j] = 0.0f;
    }
    __syncthreads();

    for (int s = 1; s <= 10; s++) {
        int m = 1 << s;
        int half = m >> 1;
        for (int k = threadIdx.x; k < MM / 2; k += blockDim.x) {
            int g  = k / half;
            int j  = k & (half - 1);
            int i1 = g * m + j;
            int i2 = i1 + half;
            float ang = (float)(-2.0 * M_PI) * (float)j / (float)m;
            float ws, wc;
            sincosf(ang, &ws, &wc);
            float xr = re[i2], xi = im[i2];
            float tr = wc * xr - ws * xi;
            float ti = wc * xi + ws * xr;
            float ur = re[i1], ui = im[i1];
            re[i1] = ur + tr;  im[i1] = ui + ti;
            re[i2] = ur - tr;  im[i2] = ui - ti;
        }
        __syncthreads();
    }

    for (int i = threadIdx.x; i < MM; i += blockDim.x)
        d_Hf[r * MM + i] = make_float2(re[i], im[i]);
}

// ---------------------------------------------------------------------------
// out[n, f] = Re( sum_r softplus(W[n,r]) e^{-i*theta*f} Hf[r,f] ),
// theta = 2*pi*tau[n,r]/M. Output is ONE float per (n,f): the harness
// allocates out_size=N*M float32 elements (complex64 coerced via astype ->
// real part). Phase per f via complex rotation recurrence; imaginary part of
// the accumulator is never needed (only the phase needs both components).
// ---------------------------------------------------------------------------
__global__ void __launch_bounds__(NB) main_kernel(
    const void* __restrict__ W,
    const void* __restrict__ tau,
    int nW, int nTau,
    float* __restrict__ outf, int capf)   // capf = out_size (float elements)
{
    __shared__ float2 hsh[RANK][FCH];

    int c  = blockIdx.x;          // f-chunk index (uniform per block)
    int f0 = c * FCH;
    int n  = blockIdx.y * NB + threadIdx.x;
    int isf32 = d_isf32;

    for (int e = threadIdx.x; e < RANK * FCH; e += NB) {
        int rr = e >> 5;          // e / FCH
        int j  = e & (FCH - 1);
        hsh[rr][j] = d_Hf[rr * MM + f0 + j];
    }
    __syncthreads();

    float accr[FCH];
#pragma unroll
    for (int j = 0; j < FCH; j++) accr[j] = 0.0f;

    const float TPOM = (float)(2.0 * M_PI / (double)MM);

#pragma unroll 2
    for (int r = 0; r < RANK; r++) {
        int idx = n * RANK + r;
        float wv = (idx < nW)   ? load_in(W,   idx, isf32) : 0.0f;
        float tv = (idx < nTau) ? load_in(tau, idx, isf32) : 0.0f;

        float wp    = log1pf(expf(wv));   // softplus(W)
        float theta = TPOM * tv;

        float s0, c0, s1, c1;
        sincosf(theta * (float)f0, &s0, &c0);   // chunk start angle
        sincosf(theta,             &s1, &c1);   // per-f step

        float pr = wp * c0, pi = -wp * s0;      // p = wp * e^{-i*theta*f0}
        float wr = c1,      wi = -s1;           // w = e^{-i*theta}

#pragma unroll
        for (int j = 0; j < FCH; j++) {
            float2 h = hsh[r][j];
            // Re(p * h)
            accr[j] = fmaf(pr, h.x, fmaf(-pi, h.y, accr[j]));
            // p *= w
            float t = pr * wr - pi * wi;
            pi = fmaf(pr, wi, pi * wr);
            pr = t;
        }
    }

    int base = n * MM + f0;
#pragma unroll
    for (int j = 0; j < FCH; j++) {
        int o = base + j;
        if (o < capf) outf[o] = accr[j];
    }
}

// ---------------------------------------------------------------------------
extern "C" void kernel_launch(void* const* d_in, const int* in_sizes, int n_in,
                              void* d_out, int out_size) {
    if (n_in < 3) return;

    const void* W   = d_in[0];
    const void* H   = d_in[1];
    const void* tau = d_in[2];
    float* outf = (float*)d_out;

    detect_kernel<<<1, 32>>>(W, in_sizes[0]);
    fft_kernel<<<RANK, 512>>>(H, in_sizes[1]);
    main_kernel<<<dim3(MM / FCH, NN / NB), NB>>>(W, tau,
                                                 in_sizes[0], in_sizes[2],
                                                 outf, out_size);
}

// round 6
// speedup vs baseline: 1.4931x; 1.4931x over previous
#include <cuda_runtime.h>
#include <math.h>

#define NN   1024
#define RANK 64
#define MM   1024
#define FCH  32    // f per block (16 packed pairs)
#define NPB  32    // n per block (1 warp)

// Scratch
__device__ float2 d_Hf[RANK * MM];     // FFT(softplus(H)), [r][f]
__device__ float4 d_prep[RANK * NN];   // (wp, theta, cos th, sin th), [r][n]

typedef unsigned long long u64;

__device__ __forceinline__ u64 pack2(float lo, float hi) {
    u64 r; asm("mov.b64 %0, {%1, %2};" : "=l"(r) : "f"(lo), "f"(hi)); return r;
}
__device__ __forceinline__ u64 bcast2(float x) { return pack2(x, x); }
__device__ __forceinline__ void unpack2(u64 v, float& lo, float& hi) {
    asm("mov.b64 {%0, %1}, %2;" : "=f"(lo), "=f"(hi) : "l"(v));
}
__device__ __forceinline__ u64 fma2(u64 a, u64 b, u64 c) {
    u64 d; asm("fma.rn.f32x2 %0, %1, %2, %3;" : "=l"(d) : "l"(a), "l"(b), "l"(c)); return d;
}
__device__ __forceinline__ u64 mul2(u64 a, u64 b) {
    u64 d; asm("mul.rn.f32x2 %0, %1, %2;" : "=l"(d) : "l"(a), "l"(b)); return d;
}

// ---------------------------------------------------------------------------
// Prep: per (n,r) transpose to [r][n] and precompute softplus(W), theta,
// cos(theta), sin(theta).  theta = 2*pi*tau/M (< 0.0062 rad: tiny args).
// ---------------------------------------------------------------------------
__global__ void prep_kernel(const float* __restrict__ W,
                            const float* __restrict__ tau, int nIn) {
    int i = blockIdx.x * blockDim.x + threadIdx.x;
    if (i >= NN * RANK) return;
    float wv = (i < nIn) ? W[i]   : 0.0f;
    float tv = (i < nIn) ? tau[i] : 0.0f;
    int n = i >> 6;          // / RANK
    int r = i & (RANK - 1);

    float wp = __logf(1.0f + __expf(wv));            // softplus
    float th = (float)(2.0 * M_PI / (double)MM) * tv;
    float s1, c1;
    __sincosf(th, &s1, &c1);
    d_prep[r * NN + n] = make_float4(wp, th, c1, s1);
}

// ---------------------------------------------------------------------------
// 1024-point radix-2 DIT FFT of softplus(H[r,:]) per block (numpy sign).
// ---------------------------------------------------------------------------
__global__ void fft_kernel(const float* __restrict__ H, int nH) {
    __shared__ float re[MM];
    __shared__ float im[MM];
    int r = blockIdx.x;

    for (int i = threadIdx.x; i < MM; i += blockDim.x) {
        int src = r * MM + i;
        float x = (src < nH) ? H[src] : 0.0f;
        float v = __logf(1.0f + __expf(x));        // softplus
        int j = (int)(__brev((unsigned)i) >> 22);  // 10-bit reversal
        re[j] = v;
        im[j] = 0.0f;
    }
    __syncthreads();

    for (int s = 1; s <= 10; s++) {
        int m = 1 << s;
        int half = m >> 1;
        for (int k = threadIdx.x; k < MM / 2; k += blockDim.x) {
            int g  = k / half;
            int j  = k & (half - 1);
            int i1 = g * m + j;
            int i2 = i1 + half;
            float ang = (float)(-2.0 * M_PI) * (float)j / (float)m;
            float ws, wc;
            __sincosf(ang, &ws, &wc);
            float xr = re[i2], xi = im[i2];
            float tr = wc * xr - ws * xi;
            float ti = wc * xi + ws * xr;
            float ur = re[i1], ui = im[i1];
            re[i1] = ur + tr;  im[i1] = ui + ti;
            re[i2] = ur - tr;  im[i2] = ui - ti;
        }
        __syncthreads();
    }

    for (int i = threadIdx.x; i < MM; i += blockDim.x)
        d_Hf[r * MM + i] = make_float2(re[i], im[i]);
}

// ---------------------------------------------------------------------------
// out[n,f] = Re( sum_r wp * e^{-i*theta*f} * Hf[r,f] ).
// Two phase chains (even/odd f) stepped by w^2, packed into f32x2 ops.
// Shared tile: Hf reals and NEGATED imags pre-packed as (f_even, f_odd).
// Grid: 32 f-chunks x 32 n-groups = 1024 one-warp blocks (~7/SM).
// ---------------------------------------------------------------------------
__global__ void __launch_bounds__(NPB) main_kernel(float* __restrict__ outf,
                                                   int capf) {
    __shared__ u64 hx2 [RANK][FCH / 2];   // (Re[2j], Re[2j+1])
    __shared__ u64 hyn2[RANK][FCH / 2];   // (-Im[2j], -Im[2j+1])

    int c  = blockIdx.x;
    int f0 = c * FCH;
    int n  = blockIdx.y * NPB + threadIdx.x;

    for (int e = threadIdx.x; e < RANK * (FCH / 2); e += NPB) {
        int rr = e >> 4;           // / 16
        int j2 = e & 15;
        float2 a = d_Hf[rr * MM + f0 + 2 * j2];
        float2 b = d_Hf[rr * MM + f0 + 2 * j2 + 1];
        hx2 [rr][j2] = pack2(a.x, b.x);
        hyn2[rr][j2] = pack2(-a.y, -b.y);
    }
    __syncthreads();

    u64 acc[FCH / 2];
#pragma unroll
    for (int j = 0; j < FCH / 2; j++) acc[j] = 0ull;

    const float f0f = (float)f0;

#pragma unroll 2
    for (int r = 0; r < RANK; r++) {
        float4 p4 = d_prep[r * NN + n];     // wp, th, cos th, sin th
        float wp = p4.x, th = p4.y, c1 = p4.z, s1 = p4.w;

        float s0, c0;
        __sincosf(th * f0f, &s0, &c0);      // chunk start angle (<= 6.2 rad)

        float prA = wp * c0, piA = -wp * s0;            // p(f0)
        float prB = fmaf(prA, c1,  piA * s1);           // p(f0+1) = pA * w
        float piB = fmaf(piA, c1, -prA * s1);
        float c2  = fmaf(c1, c1, -s1 * s1);             // cos 2th
        float s2  = 2.0f * s1 * c1;                     // sin 2th

        u64 prv  = pack2(prA, prB);
        u64 piv  = pack2(piA, piB);
        u64 w2r  = bcast2(c2);
        u64 w2i  = bcast2(-s2);    // w^2 = e^{-2i th}
        u64 w2in = bcast2(s2);

#pragma unroll
        for (int j2 = 0; j2 < FCH / 2; j2++) {
            acc[j2] = fma2(prv, hx2 [r][j2], acc[j2]);
            acc[j2] = fma2(piv, hyn2[r][j2], acc[j2]);
            u64 t = fma2(piv, w2in, mul2(prv, w2r));    // p *= w^2
            piv   = fma2(prv, w2i,  mul2(piv, w2r));
            prv   = t;
        }
    }

    int base = n * MM + f0;
#pragma unroll
    for (int j2 = 0; j2 < FCH / 2; j2++) {
        float lo, hi;
        unpack2(acc[j2], lo, hi);
        int o = base + 2 * j2;
        if (o + 1 < capf) { outf[o] = lo; outf[o + 1] = hi; }
        else if (o < capf) { outf[o] = lo; }
    }
}

// ---------------------------------------------------------------------------
extern "C" void kernel_launch(void* const* d_in, const int* in_sizes, int n_in,
                              void* d_out, int out_size) {
    if (n_in < 3) return;
    const float* W   = (const float*)d_in[0];
    const float* H   = (const float*)d_in[1];
    const float* tau = (const float*)d_in[2];
    float* outf = (float*)d_out;

    int nWT = in_sizes[0] < in_sizes[2] ? in_sizes[0] : in_sizes[2];
    prep_kernel<<<(NN * RANK + 255) / 256, 256>>>(W, tau, nWT);
    fft_kernel<<<RANK, 512>>>(H, in_sizes[1]);
    main_kernel<<<dim3(MM / FCH, NN / NPB), NPB>>>(outf, out_size);
}

// round 7
// speedup vs baseline: 1.6567x; 1.1096x over previous
#include <cuda_runtime.h>
#include <math.h>

#define NN   1024
#define RANK 64
#define MM   1024
#define FCH  32    // f per block (16 packed pairs)
#define NPB  64    // n per block (2 warps)

// Scratch
__device__ float2 d_Hf[RANK * MM];     // FFT(softplus(H)), [r][f]
__device__ float4 d_prep[RANK * NN];   // (wp, theta, cos th, sin th), [r][n]

typedef unsigned long long u64;

__device__ __forceinline__ u64 pack2(float lo, float hi) {
    u64 r; asm("mov.b64 %0, {%1, %2};" : "=l"(r) : "f"(lo), "f"(hi)); return r;
}
__device__ __forceinline__ u64 bcast2(float x) { return pack2(x, x); }
__device__ __forceinline__ void unpack2(u64 v, float& lo, float& hi) {
    asm("mov.b64 {%0, %1}, %2;" : "=f"(lo), "=f"(hi) : "l"(v));
}
__device__ __forceinline__ u64 fma2(u64 a, u64 b, u64 c) {
    u64 d; asm("fma.rn.f32x2 %0, %1, %2, %3;" : "=l"(d) : "l"(a), "l"(b), "l"(c)); return d;
}

// ---------------------------------------------------------------------------
// Fused aux kernel: blocks 0..63 do the 1024-pt radix-2 FFT of softplus(H[r]);
// blocks 64..127 do prep (softplus(W), theta, cos, sin) -> [r][n] layout.
// ---------------------------------------------------------------------------
__global__ void aux_kernel(const float* __restrict__ H, int nH,
                           const float* __restrict__ W,
                           const float* __restrict__ tau, int nWT) {
    if (blockIdx.x >= RANK) {
        // ---- prep part: 64 blocks x 512 threads, 2 elems/thread ----
        int base = (blockIdx.x - RANK) * (2 * 512);
        for (int k = 0; k < 2; k++) {
            int i = base + k * 512 + threadIdx.x;
            if (i >= NN * RANK) break;
            float wv = (i < nWT) ? W[i]   : 0.0f;
            float tv = (i < nWT) ? tau[i] : 0.0f;
            int n = i >> 6;           // / RANK
            int r = i & (RANK - 1);
            float wp = __logf(1.0f + __expf(wv));
            float th = (float)(2.0 * M_PI / (double)MM) * tv;
            float s1, c1;
            __sincosf(th, &s1, &c1);
            d_prep[r * NN + n] = make_float4(wp, th, c1, s1);
        }
        return;
    }

    // ---- FFT part (numpy sign: X[f] = sum_k x[k] e^{-2 pi i f k / M}) ----
    __shared__ float re[MM];
    __shared__ float im[MM];
    int r = blockIdx.x;

    for (int i = threadIdx.x; i < MM; i += blockDim.x) {
        int src = r * MM + i;
        float x = (src < nH) ? H[src] : 0.0f;
        float v = __logf(1.0f + __expf(x));        // softplus
        int j = (int)(__brev((unsigned)i) >> 22);  // 10-bit reversal
        re[j] = v;
        im[j] = 0.0f;
    }
    __syncthreads();

    for (int s = 1; s <= 10; s++) {
        int m = 1 << s;
        int half = m >> 1;
        for (int k = threadIdx.x; k < MM / 2; k += blockDim.x) {
            int g  = k / half;
            int j  = k & (half - 1);
            int i1 = g * m + j;
            int i2 = i1 + half;
            float ang = (float)(-2.0 * M_PI) * (float)j / (float)m;
            float ws, wc;
            __sincosf(ang, &ws, &wc);
            float xr = re[i2], xi = im[i2];
            float tr = wc * xr - ws * xi;
            float ti = wc * xi + ws * xr;
            float ur = re[i1], ui = im[i1];
            re[i1] = ur + tr;  im[i1] = ui + ti;
            re[i2] = ur - tr;  im[i2] = ui - ti;
        }
        __syncthreads();
    }

    for (int i = threadIdx.x; i < MM; i += blockDim.x)
        d_Hf[r * MM + i] = make_float2(re[i], im[i]);
}

// ---------------------------------------------------------------------------
// out[n,f] = Re( sum_r wp e^{-i theta f} Hf[r,f] ).
// Phase via sign-transformed Chebyshev recurrence: q_{t+1} = (+-K) q_t + q_{t-1}
// (K = 2cos(2 theta), sign alternating; (+,+,-,-) folded into shared tile).
// One packed FMA per chain per f-pair; 4 fma-pipe ops per (r, f-pair) total.
// ---------------------------------------------------------------------------
__global__ void __launch_bounds__(NPB) main_kernel(float* __restrict__ outf,
                                                   int capf) {
    __shared__ u64 gx[RANK][FCH / 2];   // sigma * ( Re[2t], Re[2t+1])
    __shared__ u64 gy[RANK][FCH / 2];   // sigma * (-Im[2t],-Im[2t+1])

    int c  = blockIdx.x;
    int f0 = c * FCH;
    int n  = blockIdx.y * NPB + threadIdx.x;

    for (int e = threadIdx.x; e < RANK * (FCH / 2); e += NPB) {
        int rr = e >> 4;           // / 16
        int t  = e & 15;
        float2 a = d_Hf[rr * MM + f0 + 2 * t];
        float2 b = d_Hf[rr * MM + f0 + 2 * t + 1];
        float sg = (t & 2) ? -1.0f : 1.0f;         // sigma_t = (-1)^(t/2)
        gx[rr][t] = pack2(sg * a.x, sg * b.x);
        gy[rr][t] = pack2(-sg * a.y, -sg * b.y);
    }
    __syncthreads();

    u64 acc[FCH / 2];
#pragma unroll
    for (int t = 0; t < FCH / 2; t++) acc[t] = 0ull;

    const float f0f = (float)f0;

#pragma unroll 2
    for (int r = 0; r < RANK; r++) {
        float4 p4 = d_prep[r * NN + n];     // wp, th, cos th, sin th
        float wp = p4.x, th = p4.y, c1 = p4.z, s1 = p4.w;

        float s0, c0;
        __sincosf(th * f0f, &s0, &c0);      // start angle (<= ~6.2 rad)

        float pr0 = wp * c0, pi0 = -wp * s0;             // p(f0)
        float pr1  = fmaf(pr0, c1,  pi0 * s1);           // p(f0+1) = p0*w
        float pi1  = fmaf(pi0, c1, -pr0 * s1);
        float prm1 = fmaf(pr0, c1, -pi0 * s1);           // p(f0-1) = p0*conj(w)
        float pim1 = fmaf(pi0, c1,  pr0 * s1);
        float prm2 = fmaf(prm1, c1, -pim1 * s1);         // p(f0-2)
        float pim2 = fmaf(pim1, c1,  prm1 * s1);
        float K    = fmaf(4.0f * c1, c1, -2.0f);         // 2 cos 2theta

        u64 Kp = bcast2(K), Kn = bcast2(-K);
        u64 qr_c = pack2(pr0, pr1),   qi_c = pack2(pi0, pi1);
        u64 qr_p = pack2(-prm2, -prm1), qi_p = pack2(-pim2, -pim1); // q_{-1}

#pragma unroll
        for (int t = 0; t < FCH / 2; t++) {
            acc[t] = fma2(qr_c, gx[r][t], acc[t]);
            acc[t] = fma2(qi_c, gy[r][t], acc[t]);
            u64 Kt = (t & 1) ? Kn : Kp;
            u64 nr = fma2(Kt, qr_c, qr_p);
            u64 ni = fma2(Kt, qi_c, qi_p);
            qr_p = qr_c;  qr_c = nr;
            qi_p = qi_c;  qi_c = ni;
        }
    }

    int base = n * MM + f0;
    float2* o2 = (float2*)(outf + base);
#pragma unroll
    for (int t = 0; t < FCH / 2; t++) {
        float lo, hi;
        unpack2(acc[t], lo, hi);
        int o = base + 2 * t;
        if (o + 1 < capf) o2[t] = make_float2(lo, hi);
        else if (o < capf) outf[o] = lo;
    }
}

// ---------------------------------------------------------------------------
extern "C" void kernel_launch(void* const* d_in, const int* in_sizes, int n_in,
                              void* d_out, int out_size) {
    if (n_in < 3) return;
    const float* W   = (const float*)d_in[0];
    const float* H   = (const float*)d_in[1];
    const float* tau = (const float*)d_in[2];
    float* outf = (float*)d_out;

    int nWT = in_sizes[0] < in_sizes[2] ? in_sizes[0] : in_sizes[2];
    aux_kernel<<<2 * RANK, 512>>>(H, in_sizes[1], W, tau, nWT);
    main_kernel<<<dim3(MM / FCH, NN / NPB), NPB>>>(outf, out_size);
}

// round 8
// speedup vs baseline: 1.8624x; 1.1242x over previous
#include <cuda_runtime.h>
#include <math.h>

#define NN   1024
#define RANK 64
#define MM   1024
#define FCH  16    // f per block (8 packed pairs)
#define NPB  64    // n per block (2 warps)

// Scratch
__device__ float2 d_Hf[RANK * MM];     // FFT(softplus(H)), [r][f]
__device__ float4 d_prep[RANK * NN];   // (wp, theta, cos th, sin th), [r][n]

typedef unsigned long long u64;

__device__ __forceinline__ u64 pack2(float lo, float hi) {
    u64 r; asm("mov.b64 %0, {%1, %2};" : "=l"(r) : "f"(lo), "f"(hi)); return r;
}
__device__ __forceinline__ u64 bcast2(float x) { return pack2(x, x); }
__device__ __forceinline__ void unpack2(u64 v, float& lo, float& hi) {
    asm("mov.b64 {%0, %1}, %2;" : "=f"(lo), "=f"(hi) : "l"(v));
}
__device__ __forceinline__ u64 fma2(u64 a, u64 b, u64 c) {
    u64 d; asm("fma.rn.f32x2 %0, %1, %2, %3;" : "=l"(d) : "l"(a), "l"(b), "l"(c)); return d;
}

// ---------------------------------------------------------------------------
// Fused aux kernel: blocks 0..63 do the 1024-pt radix-2 FFT of softplus(H[r]);
// blocks 64..127 do prep (softplus(W), theta, cos, sin) -> [r][n] layout.
// ---------------------------------------------------------------------------
__global__ void aux_kernel(const float* __restrict__ H, int nH,
                           const float* __restrict__ W,
                           const float* __restrict__ tau, int nWT) {
    if (blockIdx.x >= RANK) {
        // ---- prep part: 64 blocks x 512 threads, 2 elems/thread ----
        int base = (blockIdx.x - RANK) * (2 * 512);
        for (int k = 0; k < 2; k++) {
            int i = base + k * 512 + threadIdx.x;
            if (i >= NN * RANK) break;
            float wv = (i < nWT) ? W[i]   : 0.0f;
            float tv = (i < nWT) ? tau[i] : 0.0f;
            int n = i >> 6;           // / RANK
            int r = i & (RANK - 1);
            float wp = __logf(1.0f + __expf(wv));
            float th = (float)(2.0 * M_PI / (double)MM) * tv;
            float s1, c1;
            __sincosf(th, &s1, &c1);
            d_prep[r * NN + n] = make_float4(wp, th, c1, s1);
        }
        return;
    }

    // ---- FFT part (numpy sign: X[f] = sum_k x[k] e^{-2 pi i f k / M}) ----
    __shared__ float re[MM];
    __shared__ float im[MM];
    int r = blockIdx.x;

    for (int i = threadIdx.x; i < MM; i += blockDim.x) {
        int src = r * MM + i;
        float x = (src < nH) ? H[src] : 0.0f;
        float v = __logf(1.0f + __expf(x));        // softplus
        int j = (int)(__brev((unsigned)i) >> 22);  // 10-bit reversal
        re[j] = v;
        im[j] = 0.0f;
    }
    __syncthreads();

    for (int s = 1; s <= 10; s++) {
        int m = 1 << s;
        int half = m >> 1;
        for (int k = threadIdx.x; k < MM / 2; k += blockDim.x) {
            int g  = k / half;
            int j  = k & (half - 1);
            int i1 = g * m + j;
            int i2 = i1 + half;
            float ang = (float)(-2.0 * M_PI) * (float)j / (float)m;
            float ws, wc;
            __sincosf(ang, &ws, &wc);
            float xr = re[i2], xi = im[i2];
            float tr = wc * xr - ws * xi;
            float ti = wc * xi + ws * xr;
            float ur = re[i1], ui = im[i1];
            re[i1] = ur + tr;  im[i1] = ui + ti;
            re[i2] = ur - tr;  im[i2] = ui - ti;
        }
        __syncthreads();
    }

    for (int i = threadIdx.x; i < MM; i += blockDim.x)
        d_Hf[r * MM + i] = make_float2(re[i], im[i]);
}

// ---------------------------------------------------------------------------
// out[n,f] = Re( sum_r wp e^{-i theta f} Hf[r,f] ).
// Phase via sign-transformed Chebyshev recurrence: q_{t+1} = (+-K) q_t + q_{t-1}
// (K = 2cos(2 theta), alternating sign; (+,+,-,-) folded into shared tile).
// FCH=16 -> 2048 warps total (~14/SM) to cover chain + LDS latency.
// ---------------------------------------------------------------------------
__global__ void __launch_bounds__(NPB) main_kernel(float* __restrict__ outf,
                                                   int capf) {
    __shared__ u64 gx[RANK][FCH / 2];   // sigma * ( Re[2t], Re[2t+1])
    __shared__ u64 gy[RANK][FCH / 2];   // sigma * (-Im[2t],-Im[2t+1])

    int c  = blockIdx.x;
    int f0 = c * FCH;
    int n  = blockIdx.y * NPB + threadIdx.x;

    for (int e = threadIdx.x; e < RANK * (FCH / 2); e += NPB) {
        int rr = e >> 3;           // / 8
        int t  = e & 7;
        float2 a = d_Hf[rr * MM + f0 + 2 * t];
        float2 b = d_Hf[rr * MM + f0 + 2 * t + 1];
        float sg = (t & 2) ? -1.0f : 1.0f;         // sigma_t = (-1)^(t/2)
        gx[rr][t] = pack2(sg * a.x, sg * b.x);
        gy[rr][t] = pack2(-sg * a.y, -sg * b.y);
    }
    __syncthreads();

    u64 acc[FCH / 2];
#pragma unroll
    for (int t = 0; t < FCH / 2; t++) acc[t] = 0ull;

    const float f0f = (float)f0;

#pragma unroll 2
    for (int r = 0; r < RANK; r++) {
        float4 p4 = d_prep[r * NN + n];     // wp, th, cos th, sin th
        float wp = p4.x, th = p4.y, c1 = p4.z, s1 = p4.w;

        float s0, c0;
        __sincosf(th * f0f, &s0, &c0);      // start angle (<= ~6.2 rad)

        float pr0 = wp * c0, pi0 = -wp * s0;             // p(f0)
        float pr1  = fmaf(pr0, c1,  pi0 * s1);           // p(f0+1) = p0*w
        float pi1  = fmaf(pi0, c1, -pr0 * s1);
        float prm1 = fmaf(pr0, c1, -pi0 * s1);           // p(f0-1) = p0*conj(w)
        float pim1 = fmaf(pi0, c1,  pr0 * s1);
        float prm2 = fmaf(prm1, c1, -pim1 * s1);         // p(f0-2)
        float pim2 = fmaf(pim1, c1,  prm1 * s1);
        float K    = fmaf(4.0f * c1, c1, -2.0f);         // 2 cos 2theta

        u64 Kp = bcast2(K), Kn = bcast2(-K);
        u64 qr_c = pack2(pr0, pr1),   qi_c = pack2(pi0, pi1);
        u64 qr_p = pack2(-prm2, -prm1), qi_p = pack2(-pim2, -pim1); // q_{-1}

#pragma unroll
        for (int t = 0; t < FCH / 2; t++) {
            acc[t] = fma2(qr_c, gx[r][t], acc[t]);
            acc[t] = fma2(qi_c, gy[r][t], acc[t]);
            u64 Kt = (t & 1) ? Kn : Kp;
            u64 nr = fma2(Kt, qr_c, qr_p);
            u64 ni = fma2(Kt, qi_c, qi_p);
            qr_p = qr_c;  qr_c = nr;
            qi_p = qi_c;  qi_c = ni;
        }
    }

    int base = n * MM + f0;
    float2* o2 = (float2*)(outf + base);
#pragma unroll
    for (int t = 0; t < FCH / 2; t++) {
        float lo, hi;
        unpack2(acc[t], lo, hi);
        int o = base + 2 * t;
        if (o + 1 < capf) o2[t] = make_float2(lo, hi);
        else if (o < capf) outf[o] = lo;
    }
}

// ---------------------------------------------------------------------------
extern "C" void kernel_launch(void* const* d_in, const int* in_sizes, int n_in,
                              void* d_out, int out_size) {
    if (n_in < 3) return;
    const float* W   = (const float*)d_in[0];
    const float* H   = (const float*)d_in[1];
    const float* tau = (const float*)d_in[2];
    float* outf = (float*)d_out;

    int nWT = in_sizes[0] < in_sizes[2] ? in_sizes[0] : in_sizes[2];
    aux_kernel<<<2 * RANK, 512>>>(H, in_sizes[1], W, tau, nWT);
    main_kernel<<<dim3(MM / FCH, NN / NPB), NPB>>>(outf, out_size);
}

// round 9
// speedup vs baseline: 1.8786x; 1.0087x over previous
#include <cuda_runtime.h>
#include <math.h>

#define NN   1024
#define RANK 64
#define MM   1024
#define FCH  8     // f per block (4 packed pairs)
#define NPB  64    // n per block (2 warps)

// Scratch
__device__ float2 d_Hf[RANK * MM];     // FFT(softplus(H)), [r][f]
__device__ float4 d_prep[RANK * NN];   // (wp, theta, cos th, sin th), [r][n]

typedef unsigned long long u64;

__device__ __forceinline__ u64 pack2(float lo, float hi) {
    u64 r; asm("mov.b64 %0, {%1, %2};" : "=l"(r) : "f"(lo), "f"(hi)); return r;
}
__device__ __forceinline__ u64 bcast2(float x) { return pack2(x, x); }
__device__ __forceinline__ void unpack2(u64 v, float& lo, float& hi) {
    asm("mov.b64 {%0, %1}, %2;" : "=f"(lo), "=f"(hi) : "l"(v));
}
__device__ __forceinline__ u64 fma2(u64 a, u64 b, u64 c) {
    u64 d; asm("fma.rn.f32x2 %0, %1, %2, %3;" : "=l"(d) : "l"(a), "l"(b), "l"(c)); return d;
}

// ---------------------------------------------------------------------------
// Fused aux kernel: blocks 0..63 do the 1024-pt radix-2 FFT of softplus(H[r]);
// blocks 64..127 do prep (softplus(W), theta, cos, sin) -> [r][n] layout.
// ---------------------------------------------------------------------------
__global__ void aux_kernel(const float* __restrict__ H, int nH,
                           const float* __restrict__ W,
                           const float* __restrict__ tau, int nWT) {
    if (blockIdx.x >= RANK) {
        // ---- prep part: 64 blocks x 512 threads, 2 elems/thread ----
        int base = (blockIdx.x - RANK) * (2 * 512);
        for (int k = 0; k < 2; k++) {
            int i = base + k * 512 + threadIdx.x;
            if (i >= NN * RANK) break;
            float wv = (i < nWT) ? W[i]   : 0.0f;
            float tv = (i < nWT) ? tau[i] : 0.0f;
            int n = i >> 6;           // / RANK
            int r = i & (RANK - 1);
            float wp = __logf(1.0f + __expf(wv));
            float th = (float)(2.0 * M_PI / (double)MM) * tv;
            float s1, c1;
            __sincosf(th, &s1, &c1);
            d_prep[r * NN + n] = make_float4(wp, th, c1, s1);
        }
        return;
    }

    // ---- FFT part (numpy sign: X[f] = sum_k x[k] e^{-2 pi i f k / M}) ----
    __shared__ float re[MM];
    __shared__ float im[MM];
    int r = blockIdx.x;

    for (int i = threadIdx.x; i < MM; i += blockDim.x) {
        int src = r * MM + i;
        float x = (src < nH) ? H[src] : 0.0f;
        float v = __logf(1.0f + __expf(x));        // softplus
        int j = (int)(__brev((unsigned)i) >> 22);  // 10-bit reversal
        re[j] = v;
        im[j] = 0.0f;
    }
    __syncthreads();

    for (int s = 1; s <= 10; s++) {
        int m = 1 << s;
        int half = m >> 1;
        for (int k = threadIdx.x; k < MM / 2; k += blockDim.x) {
            int g  = k / half;
            int j  = k & (half - 1);
            int i1 = g * m + j;
            int i2 = i1 + half;
            float ang = (float)(-2.0 * M_PI) * (float)j / (float)m;
            float ws, wc;
            __sincosf(ang, &ws, &wc);
            float xr = re[i2], xi = im[i2];
            float tr = wc * xr - ws * xi;
            float ti = wc * xi + ws * xr;
            float ur = re[i1], ui = im[i1];
            re[i1] = ur + tr;  im[i1] = ui + ti;
            re[i2] = ur - tr;  im[i2] = ui - ti;
        }
        __syncthreads();
    }

    for (int i = threadIdx.x; i < MM; i += blockDim.x)
        d_Hf[r * MM + i] = make_float2(re[i], im[i]);
}

// ---------------------------------------------------------------------------
// out[n,f] = Re( sum_r wp e^{-i theta f} Hf[r,f] ).
// Phase via sign-transformed Chebyshev recurrence: q_{t+1} = (+-K) q_t + q_{t-1}
// (K = 2cos(2 theta), alternating sign; (+,+,-,-) folded into shared tile).
// FCH=8 -> 4096 warps (~28/SM, ~7/SMSP) to hide LDS + chain latency.
// ---------------------------------------------------------------------------
__global__ void __launch_bounds__(NPB) main_kernel(float* __restrict__ outf,
                                                   int capf) {
    __shared__ u64 gx[RANK][FCH / 2];   // sigma * ( Re[2t], Re[2t+1])
    __shared__ u64 gy[RANK][FCH / 2];   // sigma * (-Im[2t],-Im[2t+1])

    int c  = blockIdx.x;
    int f0 = c * FCH;
    int n  = blockIdx.y * NPB + threadIdx.x;

    for (int e = threadIdx.x; e < RANK * (FCH / 2); e += NPB) {
        int rr = e >> 2;           // / 4
        int t  = e & 3;
        float2 a = d_Hf[rr * MM + f0 + 2 * t];
        float2 b = d_Hf[rr * MM + f0 + 2 * t + 1];
        float sg = (t & 2) ? -1.0f : 1.0f;         // sigma_t = (-1)^(t/2)
        gx[rr][t] = pack2(sg * a.x, sg * b.x);
        gy[rr][t] = pack2(-sg * a.y, -sg * b.y);
    }
    __syncthreads();

    u64 acc[FCH / 2];
#pragma unroll
    for (int t = 0; t < FCH / 2; t++) acc[t] = 0ull;

    const float f0f = (float)f0;

#pragma unroll 2
    for (int r = 0; r < RANK; r++) {
        float4 p4 = d_prep[r * NN + n];     // wp, th, cos th, sin th
        float wp = p4.x, th = p4.y, c1 = p4.z, s1 = p4.w;

        float s0, c0;
        __sincosf(th * f0f, &s0, &c0);      // start angle (<= ~6.2 rad)

        float pr0 = wp * c0, pi0 = -wp * s0;             // p(f0)
        float pr1  = fmaf(pr0, c1,  pi0 * s1);           // p(f0+1) = p0*w
        float pi1  = fmaf(pi0, c1, -pr0 * s1);
        float prm1 = fmaf(pr0, c1, -pi0 * s1);           // p(f0-1) = p0*conj(w)
        float pim1 = fmaf(pi0, c1,  pr0 * s1);
        float prm2 = fmaf(prm1, c1, -pim1 * s1);         // p(f0-2)
        float pim2 = fmaf(pim1, c1,  prm1 * s1);
        float K    = fmaf(4.0f * c1, c1, -2.0f);         // 2 cos 2theta

        u64 Kp = bcast2(K), Kn = bcast2(-K);
        u64 qr_c = pack2(pr0, pr1),   qi_c = pack2(pi0, pi1);
        u64 qr_p = pack2(-prm2, -prm1), qi_p = pack2(-pim2, -pim1); // q_{-1}

#pragma unroll
        for (int t = 0; t < FCH / 2; t++) {
            acc[t] = fma2(qr_c, gx[r][t], acc[t]);
            acc[t] = fma2(qi_c, gy[r][t], acc[t]);
            u64 Kt = (t & 1) ? Kn : Kp;
            u64 nr = fma2(Kt, qr_c, qr_p);
            u64 ni = fma2(Kt, qi_c, qi_p);
            qr_p = qr_c;  qr_c = nr;
            qi_p = qi_c;  qi_c = ni;
        }
    }

    int base = n * MM + f0;
    float2* o2 = (float2*)(outf + base);
#pragma unroll
    for (int t = 0; t < FCH / 2; t++) {
        float lo, hi;
        unpack2(acc[t], lo, hi);
        int o = base + 2 * t;
        if (o + 1 < capf) o2[t] = make_float2(lo, hi);
        else if (o < capf) outf[o] = lo;
    }
}

// ---------------------------------------------------------------------------
extern "C" void kernel_launch(void* const* d_in, const int* in_sizes, int n_in,
                              void* d_out, int out_size) {
    if (n_in < 3) return;
    const float* W   = (const float*)d_in[0];
    const float* H   = (const float*)d_in[1];
    const float* tau = (const float*)d_in[2];
    float* outf = (float*)d_out;

    int nWT = in_sizes[0] < in_sizes[2] ? in_sizes[0] : in_sizes[2];
    aux_kernel<<<2 * RANK, 512>>>(H, in_sizes[1], W, tau, nWT);
    main_kernel<<<dim3(MM / FCH, NN / NPB), NPB>>>(outf, out_size);
}

// round 10
// speedup vs baseline: 1.9826x; 1.0553x over previous
#include <cuda_runtime.h>
#include <math.h>

#define NN   1024
#define RANK 64
#define MM   1024
#define FCH  8     // f per block (4 packed pairs)
#define NPB  64    // n per block (2 warps)

// Scratch
__device__ float2 d_Hf[RANK * MM];     // FFT(softplus(H)), [r][f]
__device__ float4 d_prep[RANK * NN];   // (wp, theta, cos th, sin th), [r][n]

typedef unsigned long long u64;

__device__ __forceinline__ u64 pack2(float lo, float hi) {
    u64 r; asm("mov.b64 %0, {%1, %2};" : "=l"(r) : "f"(lo), "f"(hi)); return r;
}
__device__ __forceinline__ u64 bcast2(float x) { return pack2(x, x); }
__device__ __forceinline__ void unpack2(u64 v, float& lo, float& hi) {
    asm("mov.b64 {%0, %1}, %2;" : "=f"(lo), "=f"(hi) : "l"(v));
}
__device__ __forceinline__ u64 fma2(u64 a, u64 b, u64 c) {
    u64 d; asm("fma.rn.f32x2 %0, %1, %2, %3;" : "=l"(d) : "l"(a), "l"(b), "l"(c)); return d;
}

// ---------------------------------------------------------------------------
// Fused aux kernel: blocks 0..63 do the 1024-pt radix-2 FFT of softplus(H[r]);
// blocks 64..127 do prep (softplus(W), theta, cos, sin) -> [r][n] layout.
// ---------------------------------------------------------------------------
__global__ void aux_kernel(const float* __restrict__ H, int nH,
                           const float* __restrict__ W,
                           const float* __restrict__ tau, int nWT) {
    if (blockIdx.x >= RANK) {
        int base = (blockIdx.x - RANK) * (2 * 512);
        for (int k = 0; k < 2; k++) {
            int i = base + k * 512 + threadIdx.x;
            if (i >= NN * RANK) break;
            float wv = (i < nWT) ? W[i]   : 0.0f;
            float tv = (i < nWT) ? tau[i] : 0.0f;
            int n = i >> 6;           // / RANK
            int r = i & (RANK - 1);
            float wp = __logf(1.0f + __expf(wv));
            float th = (float)(2.0 * M_PI / (double)MM) * tv;
            float s1, c1;
            __sincosf(th, &s1, &c1);
            d_prep[r * NN + n] = make_float4(wp, th, c1, s1);
        }
        return;
    }

    __shared__ float re[MM];
    __shared__ float im[MM];
    int r = blockIdx.x;

    for (int i = threadIdx.x; i < MM; i += blockDim.x) {
        int src = r * MM + i;
        float x = (src < nH) ? H[src] : 0.0f;
        float v = __logf(1.0f + __expf(x));        // softplus
        int j = (int)(__brev((unsigned)i) >> 22);  // 10-bit reversal
        re[j] = v;
        im[j] = 0.0f;
    }
    __syncthreads();

    for (int s = 1; s <= 10; s++) {
        int m = 1 << s;
        int half = m >> 1;
        for (int k = threadIdx.x; k < MM / 2; k += blockDim.x) {
            int g  = k / half;
            int j  = k & (half - 1);
            int i1 = g * m + j;
            int i2 = i1 + half;
            float ang = (float)(-2.0 * M_PI) * (float)j / (float)m;
            float ws, wc;
            __sincosf(ang, &ws, &wc);
            float xr = re[i2], xi = im[i2];
            float tr = wc * xr - ws * xi;
            float ti = wc * xi + ws * xr;
            float ur = re[i1], ui = im[i1];
            re[i1] = ur + tr;  im[i1] = ui + ti;
            re[i2] = ur - tr;  im[i2] = ui - ti;
        }
        __syncthreads();
    }

    for (int i = threadIdx.x; i < MM; i += blockDim.x)
        d_Hf[r * MM + i] = make_float2(re[i], im[i]);
}

// ---------------------------------------------------------------------------
// out[n,f] = Re( sum_r wp e^{-i theta f} Hf[r,f] ).
// Sign-transformed Chebyshev recurrence (pure FMA chain), f32x2-packed.
// This round: 4-deep d_prep prefetch pipeline (MLP 4), fused LDS.128 tile
// loads (gx|gy interleaved), STG.128 output.
// ---------------------------------------------------------------------------
__global__ void __launch_bounds__(NPB) main_kernel(float* __restrict__ outf,
                                                   int capf) {
    __shared__ ulonglong2 g[RANK][FCH / 2];  // .x = sg*(Re,Re'), .y = sg*(-Im,-Im')

    int c  = blockIdx.x;
    int f0 = c * FCH;
    int n  = blockIdx.y * NPB + threadIdx.x;

    for (int e = threadIdx.x; e < RANK * (FCH / 2); e += NPB) {
        int rr = e >> 2;           // / 4
        int t  = e & 3;
        float4 ab = *(const float4*)&d_Hf[rr * MM + f0 + 2 * t];
        float sg = (t & 2) ? -1.0f : 1.0f;          // sigma_t = (-1)^(t/2)
        g[rr][t] = make_ulonglong2(pack2(sg * ab.x, sg * ab.z),
                                   pack2(-sg * ab.y, -sg * ab.w));
    }
    __syncthreads();

    u64 acc[FCH / 2];
#pragma unroll
    for (int t = 0; t < FCH / 2; t++) acc[t] = 0ull;

    const float f0f = (float)f0;

    // 4-deep prefetch pipeline over r.
    float4 pb[4];
#pragma unroll
    for (int k = 0; k < 4; k++) pb[k] = d_prep[k * NN + n];

    for (int r0 = 0; r0 < RANK; r0 += 4) {
        float4 pn[4];
        if (r0 + 4 < RANK) {
#pragma unroll
            for (int k = 0; k < 4; k++) pn[k] = d_prep[(r0 + 4 + k) * NN + n];
        }

#pragma unroll
        for (int k = 0; k < 4; k++) {
            int r = r0 + k;
            float wp = pb[k].x, th = pb[k].y, c1 = pb[k].z, s1 = pb[k].w;

            float s0, c0;
            __sincosf(th * f0f, &s0, &c0);          // start angle (<= ~6.2 rad)

            float pr0 = wp * c0, pi0 = -wp * s0;              // p(f0)
            float pr1  = fmaf(pr0, c1,  pi0 * s1);            // p(f0+1)
            float pi1  = fmaf(pi0, c1, -pr0 * s1);
            float prm1 = fmaf(pr0, c1, -pi0 * s1);            // p(f0-1)
            float pim1 = fmaf(pi0, c1,  pr0 * s1);
            float prm2 = fmaf(prm1, c1, -pim1 * s1);          // p(f0-2)
            float pim2 = fmaf(pim1, c1,  prm1 * s1);
            float K    = fmaf(4.0f * c1, c1, -2.0f);          // 2 cos 2theta

            u64 Kp = bcast2(K), Kn = bcast2(-K);
            u64 qr_c = pack2(pr0, pr1),     qi_c = pack2(pi0, pi1);
            u64 qr_p = pack2(-prm2, -prm1), qi_p = pack2(-pim2, -pim1);

#pragma unroll
            for (int t = 0; t < FCH / 2; t++) {
                ulonglong2 gv = g[r][t];            // one LDS.128
                acc[t] = fma2(qr_c, gv.x, acc[t]);
                acc[t] = fma2(qi_c, gv.y, acc[t]);
                u64 Kt = (t & 1) ? Kn : Kp;
                u64 nr = fma2(Kt, qr_c, qr_p);
                u64 ni = fma2(Kt, qi_c, qi_p);
                qr_p = qr_c;  qr_c = nr;
                qi_p = qi_c;  qi_c = ni;
            }
        }

#pragma unroll
        for (int k = 0; k < 4; k++) pb[k] = pn[k];
    }

    int base = n * MM + f0;
    if (base + FCH <= capf) {
        // two STG.128 (base is 32B aligned: f0 multiple of 8)
        float4* o4 = (float4*)(outf + base);
        float a0, a1, b0, b1;
        unpack2(acc[0], a0, a1);  unpack2(acc[1], b0, b1);
        o4[0] = make_float4(a0, a1, b0, b1);
        unpack2(acc[2], a0, a1);  unpack2(acc[3], b0, b1);
        o4[1] = make_float4(a0, a1, b0, b1);
    } else {
#pragma unroll
        for (int t = 0; t < FCH / 2; t++) {
            float lo, hi;
            unpack2(acc[t], lo, hi);
            int o = base + 2 * t;
            if (o < capf)     outf[o]     = lo;
            if (o + 1 < capf) outf[o + 1] = hi;
        }
    }
}

// ---------------------------------------------------------------------------
extern "C" void kernel_launch(void* const* d_in, const int* in_sizes, int n_in,
                              void* d_out, int out_size) {
    if (n_in < 3) return;
    const float* W   = (const float*)d_in[0];
    const float* H   = (const float*)d_in[1];
    const float* tau = (const float*)d_in[2];
    float* outf = (float*)d_out;

    int nWT = in_sizes[0] < in_sizes[2] ? in_sizes[0] : in_sizes[2];
    aux_kernel<<<2 * RANK, 512>>>(H, in_sizes[1], W, tau, nWT);
    main_kernel<<<dim3(MM / FCH, NN / NPB), NPB>>>(outf, out_size);
}

// round 11
// speedup vs baseline: 2.1240x; 1.0714x over previous
#include <cuda_runtime.h>
#include <math.h>

#define NN   1024
#define RANK 64
#define MM   1024
#define FCH  8     // f per block (4 packed pairs)
#define NSL  64    // n-slice per block
#define NTH  128   // threads per block (2 r-halves x 64 n)

// Scratch
__device__ float2 d_Hf[RANK * MM];     // FFT(softplus(H)), [r][f]
__device__ float4 d_prep[RANK * NN];   // (wp, theta, cos th, sin th), [r][n]

typedef unsigned long long u64;

__device__ __forceinline__ u64 pack2(float lo, float hi) {
    u64 r; asm("mov.b64 %0, {%1, %2};" : "=l"(r) : "f"(lo), "f"(hi)); return r;
}
__device__ __forceinline__ u64 bcast2(float x) { return pack2(x, x); }
__device__ __forceinline__ void unpack2(u64 v, float& lo, float& hi) {
    asm("mov.b64 {%0, %1}, %2;" : "=f"(lo), "=f"(hi) : "l"(v));
}
__device__ __forceinline__ u64 fma2(u64 a, u64 b, u64 c) {
    u64 d; asm("fma.rn.f32x2 %0, %1, %2, %3;" : "=l"(d) : "l"(a), "l"(b), "l"(c)); return d;
}
__device__ __forceinline__ u64 add2(u64 a, u64 b) {
    u64 d; asm("add.rn.f32x2 %0, %1, %2;" : "=l"(d) : "l"(a), "l"(b)); return d;
}

// ---------------------------------------------------------------------------
// Fused aux kernel: blocks 0..63 do the 1024-pt radix-2 FFT of softplus(H[r]);
// blocks 64..127 do prep (softplus(W), theta, cos, sin) -> [r][n] layout.
// ---------------------------------------------------------------------------
__global__ void aux_kernel(const float* __restrict__ H, int nH,
                           const float* __restrict__ W,
                           const float* __restrict__ tau, int nWT) {
    if (blockIdx.x >= RANK) {
        int base = (blockIdx.x - RANK) * (2 * 512);
        for (int k = 0; k < 2; k++) {
            int i = base + k * 512 + threadIdx.x;
            if (i >= NN * RANK) break;
            float wv = (i < nWT) ? W[i]   : 0.0f;
            float tv = (i < nWT) ? tau[i] : 0.0f;
            int n = i >> 6;           // / RANK
            int r = i & (RANK - 1);
            float wp = __logf(1.0f + __expf(wv));
            float th = (float)(2.0 * M_PI / (double)MM) * tv;
            float s1, c1;
            __sincosf(th, &s1, &c1);
            d_prep[r * NN + n] = make_float4(wp, th, c1, s1);
        }
        return;
    }

    __shared__ float re[MM];
    __shared__ float im[MM];
    int r = blockIdx.x;

    for (int i = threadIdx.x; i < MM; i += blockDim.x) {
        int src = r * MM + i;
        float x = (src < nH) ? H[src] : 0.0f;
        float v = __logf(1.0f + __expf(x));        // softplus
        int j = (int)(__brev((unsigned)i) >> 22);  // 10-bit reversal
        re[j] = v;
        im[j] = 0.0f;
    }
    __syncthreads();

    for (int s = 1; s <= 10; s++) {
        int m = 1 << s;
        int half = m >> 1;
        for (int k = threadIdx.x; k < MM / 2; k += blockDim.x) {
            int g  = k / half;
            int j  = k & (half - 1);
            int i1 = g * m + j;
            int i2 = i1 + half;
            float ang = (float)(-2.0 * M_PI) * (float)j / (float)m;
            float ws, wc;
            __sincosf(ang, &ws, &wc);
            float xr = re[i2], xi = im[i2];
            float tr = wc * xr - ws * xi;
            float ti = wc * xi + ws * xr;
            float ur = re[i1], ui = im[i1];
            re[i1] = ur + tr;  im[i1] = ui + ti;
            re[i2] = ur - tr;  im[i2] = ui - ti;
        }
        __syncthreads();
    }

    for (int i = threadIdx.x; i < MM; i += blockDim.x)
        d_Hf[r * MM + i] = make_float2(re[i], im[i]);
}

// ---------------------------------------------------------------------------
// out[n,f] = Re( sum_r wp e^{-i theta f} Hf[r,f] ).
// Sign-transformed Chebyshev recurrence (pure FMA chain), f32x2-packed.
// This round: r-sum SPLIT across two thread groups (r in [0,32) / [32,64))
// for the same (n, chunk); partials combined via shared memory. Doubles warp
// parallelism (8192 warps, ~14/SMSP) without duplicating per-r setup.
// ---------------------------------------------------------------------------
__global__ void __launch_bounds__(NTH) main_kernel(float* __restrict__ outf,
                                                   int capf) {
    __shared__ ulonglong2 g[RANK][FCH / 2];  // .x = sg*(Re,Re'), .y = sg*(-Im,-Im')
    __shared__ u64 comb[NSL][FCH / 2];       // partial sums from r-half 1

    int c  = blockIdx.x;
    int f0 = c * FCH;
    int t  = threadIdx.x;
    int ln = t & (NSL - 1);          // n within slice
    int rh = t >> 6;                 // r-half: 0 or 1
    int n  = blockIdx.y * NSL + ln;

    for (int e = t; e < RANK * (FCH / 2); e += NTH) {
        int rr = e >> 2;             // / 4
        int tt = e & 3;
        float4 ab = *(const float4*)&d_Hf[rr * MM + f0 + 2 * tt];
        float sg = (tt & 2) ? -1.0f : 1.0f;          // sigma_t = (-1)^(t/2)
        g[rr][tt] = make_ulonglong2(pack2(sg * ab.x, sg * ab.z),
                                    pack2(-sg * ab.y, -sg * ab.w));
    }
    __syncthreads();

    u64 acc[FCH / 2];
#pragma unroll
    for (int q = 0; q < FCH / 2; q++) acc[q] = 0ull;

    const float f0f = (float)f0;
    const int rbeg = rh * (RANK / 2);
    const float4* prep = &d_prep[rbeg * NN + n];

    // 4-deep prefetch pipeline over this thread's 32 r's.
    float4 pb[4];
#pragma unroll
    for (int k = 0; k < 4; k++) pb[k] = prep[k * NN];

    for (int r0 = 0; r0 < RANK / 2; r0 += 4) {
        float4 pn[4];
        if (r0 + 4 < RANK / 2) {
#pragma unroll
            for (int k = 0; k < 4; k++) pn[k] = prep[(r0 + 4 + k) * NN];
        }

#pragma unroll
        for (int k = 0; k < 4; k++) {
            int r = rbeg + r0 + k;
            float wp = pb[k].x, th = pb[k].y, c1 = pb[k].z, s1 = pb[k].w;

            float s0, c0;
            __sincosf(th * f0f, &s0, &c0);          // start angle (<= ~6.2 rad)

            float pr0 = wp * c0, pi0 = -wp * s0;              // p(f0)
            float pr1  = fmaf(pr0, c1,  pi0 * s1);            // p(f0+1)
            float pi1  = fmaf(pi0, c1, -pr0 * s1);
            float prm1 = fmaf(pr0, c1, -pi0 * s1);            // p(f0-1)
            float pim1 = fmaf(pi0, c1,  pr0 * s1);
            float prm2 = fmaf(prm1, c1, -pim1 * s1);          // p(f0-2)
            float pim2 = fmaf(pim1, c1,  prm1 * s1);
            float K    = fmaf(4.0f * c1, c1, -2.0f);          // 2 cos 2theta

            u64 Kp = bcast2(K), Kn = bcast2(-K);
            u64 qr_c = pack2(pr0, pr1),     qi_c = pack2(pi0, pi1);
            u64 qr_p = pack2(-prm2, -prm1), qi_p = pack2(-pim2, -pim1);

#pragma unroll
            for (int tt = 0; tt < FCH / 2; tt++) {
                ulonglong2 gv = g[r][tt];           // one LDS.128
                acc[tt] = fma2(qr_c, gv.x, acc[tt]);
                acc[tt] = fma2(qi_c, gv.y, acc[tt]);
                u64 Kt = (tt & 1) ? Kn : Kp;
                u64 nr = fma2(Kt, qr_c, qr_p);
                u64 ni = fma2(Kt, qi_c, qi_p);
                qr_p = qr_c;  qr_c = nr;
                qi_p = qi_c;  qi_c = ni;
            }
        }

#pragma unroll
        for (int k = 0; k < 4; k++) pb[k] = pn[k];
    }

    // Combine the two r-halves.
    if (rh) {
#pragma unroll
        for (int q = 0; q < FCH / 2; q++) comb[ln][q] = acc[q];
    }
    __syncthreads();
    if (rh) return;

#pragma unroll
    for (int q = 0; q < FCH / 2; q++) acc[q] = add2(acc[q], comb[ln][q]);

    int base = n * MM + f0;
    if (base + FCH <= capf) {
        float4* o4 = (float4*)(outf + base);       // 32B aligned (f0 % 8 == 0)
        float a0, a1, b0, b1;
        unpack2(acc[0], a0, a1);  unpack2(acc[1], b0, b1);
        o4[0] = make_float4(a0, a1, b0, b1);
        unpack2(acc[2], a0, a1);  unpack2(acc[3], b0, b1);
        o4[1] = make_float4(a0, a1, b0, b1);
    } else {
#pragma unroll
        for (int q = 0; q < FCH / 2; q++) {
            float lo, hi;
            unpack2(acc[q], lo, hi);
            int o = base + 2 * q;
            if (o < capf)     outf[o]     = lo;
            if (o + 1 < capf) outf[o + 1] = hi;
        }
    }
}

// ---------------------------------------------------------------------------
extern "C" void kernel_launch(void* const* d_in, const int* in_sizes, int n_in,
                              void* d_out, int out_size) {
    if (n_in < 3) return;
    const float* W   = (const float*)d_in[0];
    const float* H   = (const float*)d_in[1];
    const float* tau = (const float*)d_in[2];
    float* outf = (float*)d_out;

    int nWT = in_sizes[0] < in_sizes[2] ? in_sizes[0] : in_sizes[2];
    aux_kernel<<<2 * RANK, 512>>>(H, in_sizes[1], W, tau, nWT);
    main_kernel<<<dim3(MM / FCH, NN / NSL), NTH>>>(outf, out_size);
}